// round 15
// baseline (speedup 1.0000x reference)
#include <cuda_runtime.h>
#include <cuda_fp16.h>
#include <math.h>
#include <stdint.h>

// ---------------------------------------------------------------------------
// Problem constants
// ---------------------------------------------------------------------------
#define T_SEQ    2048
#define D_MODEL  2048
#define N_HEADS  32
#define N_KV     8
#define HEAD_DIM 64
#define KV_DIM   (N_KV * HEAD_DIM)       // 512
#define QKV_N    (D_MODEL + 2 * KV_DIM)  // 3072
#define WINDOW_HALF 256

// ---------------------------------------------------------------------------
// Scratch (device globals; no allocation allowed)
// ---------------------------------------------------------------------------
__device__ __half g_Qhf[(size_t)T_SEQ * D_MODEL];  // fp16 Q (roped in-place)
__device__ __half g_Khf[(size_t)T_SEQ * KV_DIM];   // fp16 K (roped in-place)
__device__ __half g_Vhf[(size_t)T_SEQ * KV_DIM];   // fp16 V (final)
__device__ __half g_Xh[(size_t)T_SEQ * D_MODEL];
__device__ __half g_Wh[(size_t)QKV_N * D_MODEL];
__device__ __half g_Woh[(size_t)D_MODEL * D_MODEL];
__device__ __half g_Oh[(size_t)T_SEQ * D_MODEL];
__device__ float  g_cos[T_SEQ * 32];
__device__ float  g_sin[T_SEQ * 32];

// ---------------------------------------------------------------------------
// helpers
// ---------------------------------------------------------------------------
__device__ __forceinline__ unsigned smem_u32(const void* p)
{
    unsigned a;
    asm("{ .reg .u64 t; cvta.to.shared.u64 t, %1; cvt.u32.u64 %0, t; }" : "=r"(a) : "l"(p));
    return a;
}

__device__ __forceinline__ void mma_fp16(float* c, const unsigned* a, const unsigned* b)
{
    asm volatile(
        "mma.sync.aligned.m16n8k16.row.col.f32.f16.f16.f32 "
        "{%0,%1,%2,%3}, {%4,%5,%6,%7}, {%8,%9}, {%0,%1,%2,%3};"
        : "+f"(c[0]), "+f"(c[1]), "+f"(c[2]), "+f"(c[3])
        : "r"(a[0]), "r"(a[1]), "r"(a[2]), "r"(a[3]),
          "r"(b[0]), "r"(b[1]));
}

__device__ __forceinline__ void ldsm_x4(unsigned* r, unsigned addr)
{
    asm volatile("ldmatrix.sync.aligned.m8n8.x4.shared.b16 {%0,%1,%2,%3}, [%4];"
                 : "=r"(r[0]), "=r"(r[1]), "=r"(r[2]), "=r"(r[3]) : "r"(addr));
}

__device__ __forceinline__ void ldsm_x4_t(unsigned* r, unsigned addr)
{
    asm volatile("ldmatrix.sync.aligned.m8n8.x4.trans.shared.b16 {%0,%1,%2,%3}, [%4];"
                 : "=r"(r[0]), "=r"(r[1]), "=r"(r[2]), "=r"(r[3]) : "r"(addr));
}

__device__ __forceinline__ void cp16(unsigned dst, const void* src)
{
    asm volatile("cp.async.ca.shared.global [%0], [%1], 16;" :: "r"(dst), "l"(src));
}

__device__ __forceinline__ unsigned h2u(__half2 h) { return *(unsigned*)&h; }

// ---------------------------------------------------------------------------
// Fused prep kernel #1: RoPE cos/sin tables (first TBL_BLOCKS blocks) +
// fp32->fp16 conversion of X, Wqkv, Wo (8 floats / thread).
// ---------------------------------------------------------------------------
#define TBL_N      (T_SEQ * 32)
#define TBL_BLOCKS (TBL_N / 256)          // 256
#define N8_X   (T_SEQ * D_MODEL / 8)
#define N8_WQ  (D_MODEL * D_MODEL / 8)
#define N8_WKV (KV_DIM * D_MODEL / 8)
#define N8_WO  (D_MODEL * D_MODEL / 8)
#define N8_TOT (N8_X + N8_WQ + 2 * N8_WKV + N8_WO)
#define SPLIT_BLOCKS (TBL_BLOCKS + (N8_TOT + 255) / 256)

__global__ void split_all(const float* __restrict__ X,  const float* __restrict__ Wq,
                          const float* __restrict__ Wk, const float* __restrict__ Wv,
                          const float* __restrict__ Wo,
                          __half* __restrict__ Xh, __half* __restrict__ Wh,
                          __half* __restrict__ Woh)
{
    if (blockIdx.x < TBL_BLOCKS) {
        int idx = blockIdx.x * blockDim.x + threadIdx.x;
        int i = idx & 31;
        int t = idx >> 5;
        double invf = exp2(-(double)i / 32.0 * 13.287712379549449392);
        double ang  = fmod((double)t * invf, 6.28318530717958647692);
        g_cos[idx] = cosf((float)ang);
        g_sin[idx] = sinf((float)ang);
        return;
    }
    int i = (blockIdx.x - TBL_BLOCKS) * blockDim.x + threadIdx.x;
    if (i >= N8_TOT) return;

    const float* s; __half* hp; int off;
    if (i < N8_X)                         { off = i;                           s = X;  hp = Xh; }
    else if (i < N8_X + N8_WQ)            { off = i - N8_X;                    s = Wq; hp = Wh; }
    else if (i < N8_X + N8_WQ + N8_WKV)   { off = i - N8_X - N8_WQ;            s = Wk;
                                            hp = Wh + (size_t)D_MODEL * D_MODEL; }
    else if (i < N8_X + N8_WQ + 2*N8_WKV) { off = i - N8_X - N8_WQ - N8_WKV;   s = Wv;
                                            hp = Wh + (size_t)(D_MODEL + KV_DIM) * D_MODEL; }
    else                                  { off = i - N8_X - N8_WQ - 2*N8_WKV; s = Wo; hp = Woh; }

    float4 v0 = ((const float4*)s)[2 * off];
    float4 v1 = ((const float4*)s)[2 * off + 1];
    uint4 w;
    w.x = h2u(__floats2half2_rn(v0.x, v0.y));
    w.y = h2u(__floats2half2_rn(v0.z, v0.w));
    w.z = h2u(__floats2half2_rn(v1.x, v1.y));
    w.w = h2u(__floats2half2_rn(v1.z, v1.w));
    ((uint4*)hp)[off] = w;
}

// ---------------------------------------------------------------------------
// fp16 single-pass tensor-core GEMM; output dtype templated (fp32 or fp16).
// ---------------------------------------------------------------------------
#define BM 128
#define BN 128
#define GBK 32
#define KPAD 40
#define PLANE_E (128 * KPAD)
#define PLANE_BYTES (PLANE_E * 2)
#define STAGE_B (2 * PLANE_BYTES)
#define GEMM_SMEM (2 * STAGE_B)

__device__ __forceinline__ void stage_fp(unsigned sbase,
                                         const __half* A, const __half* B,
                                         int K, int bm, int bn, int k0, int tid)
{
#pragma unroll
    for (int t = 0; t < 4; t++) {
        int id = tid + t * 256;
        int plane = id >> 9;
        int r = (id >> 2) & 127;
        int c = id & 3;
        unsigned dst = sbase + (unsigned)(plane * PLANE_E + r * KPAD + c * 8) * 2u;
        const __half* src = (plane == 0)
            ? A + (size_t)(bm + r) * K + k0 + c * 8
            : B + (size_t)(bn + r) * K + k0 + c * 8;
        cp16(dst, src);
    }
}

template<typename TO>
__global__ void __launch_bounds__(256, 2)
gemm_fp1(const __half* __restrict__ A, const __half* __restrict__ B, int K,
         TO* __restrict__ C0, int n0, int s0,
         TO* __restrict__ C1, int n1, int s1,
         TO* __restrict__ C2, int s2)
{
    extern __shared__ __half smb[];
    unsigned sbase = smem_u32(smb);

    const int tid = threadIdx.x;
    const int bm = blockIdx.y * BM;
    const int bn = blockIdx.x * BN;

    const int warp = tid >> 5;
    const int lane = tid & 31;
    const int qr = lane >> 2;
    const int qc = lane & 3;
    const int wr = warp >> 2;
    const int wc = warp & 3;

    const int lane8 = lane & 7;
    const int mat   = lane >> 3;
    const unsigned a_e = (unsigned)((wr * 64 + (mat & 1) * 8 + lane8) * KPAD + (mat >> 1) * 8);
    const unsigned b_e = (unsigned)((wc * 32 + (mat & 1) * 8 + lane8) * KPAD + (mat >> 1) * 8);

    float acc[4][4][4];
#pragma unroll
    for (int i = 0; i < 4; i++)
#pragma unroll
        for (int j = 0; j < 4; j++)
#pragma unroll
            for (int r = 0; r < 4; r++) acc[i][j][r] = 0.f;

    const int NS = K / GBK;

    stage_fp(sbase, A, B, K, bm, bn, 0, tid);
    asm volatile("cp.async.commit_group;" ::: "memory");
    stage_fp(sbase + STAGE_B, A, B, K, bm, bn, GBK, tid);
    asm volatile("cp.async.commit_group;" ::: "memory");

    for (int s = 0; s < NS; s++) {
        asm volatile("cp.async.wait_group 1;" ::: "memory");
        __syncthreads();

        const int buf = s & 1;
        const unsigned stg = sbase + buf * STAGE_B;
        const unsigned aP = stg + a_e * 2;
        const unsigned bP = stg + PLANE_BYTES + b_e * 2;

#pragma unroll
        for (int ks = 0; ks < GBK; ks += 16) {
            unsigned bh[2][4];
#pragma unroll
            for (int n2 = 0; n2 < 2; n2++)
                ldsm_x4(bh[n2], bP + n2 * (16 * KPAD * 2) + ks * 2);
#pragma unroll
            for (int mt = 0; mt < 4; mt++) {
                unsigned ah[4];
                ldsm_x4(ah, aP + mt * (16 * KPAD * 2) + ks * 2);
#pragma unroll
                for (int nt = 0; nt < 4; nt++) {
                    const int n2 = nt >> 1, od = nt & 1;
                    unsigned bf[2] = {bh[n2][od], bh[n2][od + 2]};
                    mma_fp16(acc[mt][nt], ah, bf);
                }
            }
        }
        __syncthreads();

        if (s + 2 < NS)
            stage_fp(sbase + buf * STAGE_B, A, B, K, bm, bn, (s + 2) * GBK, tid);
        asm volatile("cp.async.commit_group;" ::: "memory");
    }

    TO* C; int col0, stride;
    if (bn < n0)      { C = C0; col0 = bn;      stride = s0; }
    else if (bn < n1) { C = C1; col0 = bn - n0; stride = s1; }
    else              { C = C2; col0 = bn - n1; stride = s2; }

#pragma unroll
    for (int mt = 0; mt < 4; mt++) {
        const int row0 = bm + wr * 64 + mt * 16 + qr;
#pragma unroll
        for (int nt = 0; nt < 4; nt++) {
            const int col = col0 + wc * 32 + nt * 8 + qc * 2;
            if (sizeof(TO) == 2) {
                *(__half2*)((__half*)C + (size_t)row0       * stride + col) =
                    __floats2half2_rn(acc[mt][nt][0], acc[mt][nt][1]);
                *(__half2*)((__half*)C + (size_t)(row0 + 8) * stride + col) =
                    __floats2half2_rn(acc[mt][nt][2], acc[mt][nt][3]);
            } else {
                *(float2*)((float*)C + (size_t)row0       * stride + col) =
                    make_float2(acc[mt][nt][0], acc[mt][nt][1]);
                *(float2*)((float*)C + (size_t)(row0 + 8) * stride + col) =
                    make_float2(acc[mt][nt][2], acc[mt][nt][3]);
            }
        }
    }
}

// ---------------------------------------------------------------------------
// qkv_prep: in-place RoPE of fp16 Q (per head) and fp16 K (fp32 math).
// ---------------------------------------------------------------------------
#define PREP_Q  (T_SEQ * N_HEADS * 8)   // 524288
#define PREP_K  (T_SEQ * N_KV * 8)      // 131072
#define PREP_TOT (PREP_Q + PREP_K)

__device__ __forceinline__ void rope4_inplace(__half* p, const float* cs, const float* sn)
{
    __half2 a01 = *(__half2*)(p);
    __half2 a23 = *(__half2*)(p + 2);
    __half2 b01 = *(__half2*)(p + 32);
    __half2 b23 = *(__half2*)(p + 34);
    float2 a0 = __half22float2(a01), a1 = __half22float2(a23);
    float2 b0 = __half22float2(b01), b1 = __half22float2(b23);
    *(__half2*)(p)      = __floats2half2_rn(a0.x * cs[0] - b0.x * sn[0], a0.y * cs[1] - b0.y * sn[1]);
    *(__half2*)(p + 2)  = __floats2half2_rn(a1.x * cs[2] - b1.x * sn[2], a1.y * cs[3] - b1.y * sn[3]);
    *(__half2*)(p + 32) = __floats2half2_rn(b0.x * cs[0] + a0.x * sn[0], b0.y * cs[1] + a0.y * sn[1]);
    *(__half2*)(p + 34) = __floats2half2_rn(b1.x * cs[2] + a1.x * sn[2], b1.y * cs[3] + a1.y * sn[3]);
}

__global__ void qkv_prep(__half* __restrict__ Qhf, __half* __restrict__ Khf)
{
    int idx = blockIdx.x * blockDim.x + threadIdx.x;
    if (idx >= PREP_TOT) return;

    if (idx < PREP_Q) {
        int d4 = (idx & 7) * 4;
        int h  = (idx >> 3) & 31;
        int t  = idx >> 8;
        float4 cs = *(const float4*)(g_cos + t * 32 + d4);
        float4 sn = *(const float4*)(g_sin + t * 32 + d4);
        rope4_inplace(Qhf + (size_t)t * D_MODEL + h * HEAD_DIM + d4, (const float*)&cs, (const float*)&sn);
    } else {
        idx -= PREP_Q;
        int d4 = (idx & 7) * 4;
        int g  = (idx >> 3) & 7;
        int t  = idx >> 6;
        float4 cs = *(const float4*)(g_cos + t * 32 + d4);
        float4 sn = *(const float4*)(g_sin + t * 32 + d4);
        rope4_inplace(Khf + (size_t)t * KV_DIM + g * HEAD_DIM + d4, (const float*)&cs, (const float*)&sn);
    }
}

// ---------------------------------------------------------------------------
// fp16 tensor-core banded GQA attention: 2 heads / block, prepped fp16 Q/K/V,
// double-buffered K/V chunks. Register-slimmed for 3 CTAs/SM:
//   - P has its own smem region (Qs stays intact; Q frags reloaded per k-step)
//   - S/softmax computed in two nt-halves (sfr live halved)
// ---------------------------------------------------------------------------
#define QT  64
#define CHK 64
#define AP  72
#define Q_BYTES   (2 * QT * AP * 2)            // 18432
#define KV_BUF_B  (CHK * AP * 2)               // 9216
#define P_BYTES   (2 * QT * AP * 2)            // 18432
#define ATTN_SMEM (Q_BYTES + 4 * KV_BUF_B + P_BYTES)  // 73728 -> 3 CTAs/SM

__device__ __forceinline__ void stage_kv(unsigned dK, unsigned dV,
                                         const __half* Kg, const __half* Vg,
                                         int c, int tid)
{
    const int r  = tid >> 2;
    const int u0 = (tid & 3) * 2;
    const __half* ks = Kg + (size_t)(c + r) * KV_DIM;
    const __half* vs = Vg + (size_t)(c + r) * KV_DIM;
#pragma unroll
    for (int u = 0; u < 2; u++) {
        cp16(dK + (unsigned)(r * AP + (u0 + u) * 8) * 2u, ks + (u0 + u) * 8);
        cp16(dV + (unsigned)(r * AP + (u0 + u) * 8) * 2u, vs + (u0 + u) * 8);
    }
}

__global__ void __launch_bounds__(256, 3)
attn_fp16(const __half* __restrict__ Qhf, const __half* __restrict__ Khf,
          const __half* __restrict__ Vhf, __half* __restrict__ Oh)
{
    extern __shared__ __half smA[];
    __half* Ps = smA + (Q_BYTES + 4 * KV_BUF_B) / 2;
    const unsigned sQ = smem_u32(smA);
    const unsigned sK = sQ + Q_BYTES;
    const unsigned sV = sK + 2 * KV_BUF_B;
    const unsigned sP = sV + 2 * KV_BUF_B;

    const int h0 = blockIdx.y * 2;
    const int g  = h0 >> 2;
    const int q0 = blockIdx.x * QT;
    const int tid = threadIdx.x;
    const int w = tid >> 5;
    const int lane = tid & 31;
    const int qr = lane >> 2;
    const int qc = lane & 3;
    const int lane8 = lane & 7;
    const int mat   = lane >> 3;

    const int hl = w >> 2;
    const int wq = w & 3;

    const unsigned q_e = (unsigned)((hl * 64 + wq * 16 + (mat & 1) * 8 + lane8) * AP + (mat >> 1) * 8);
    const unsigned k_e = (unsigned)(((mat & 1) * 8 + lane8) * AP + (mat >> 1) * 8);
    const unsigned v_e = (unsigned)(((mat >> 1) * 8 + lane8) * AP + (mat & 1) * 8);

    const __half* Kg = Khf + g * HEAD_DIM;
    const __half* Vg = Vhf + g * HEAD_DIM;

    const int jstart = max(0, q0 - WINDOW_HALF);
    const int jend   = min(T_SEQ, q0 + QT + WINDOW_HALF);
    const int nch    = (jend - jstart) / CHK;

    stage_kv(sK, sV, Kg, Vg, jstart, tid);
    asm volatile("cp.async.commit_group;" ::: "memory");
#pragma unroll
    for (int t = 0; t < 4; t++) {
        int idx = tid + t * 256;
        int rr  = idx >> 3;
        int u   = idx & 7;
        int hloc = rr >> 6;
        int r    = rr & 63;
        const __half* src = Qhf + (size_t)(q0 + r) * D_MODEL + (h0 + hloc) * HEAD_DIM + u * 8;
        cp16(sQ + (unsigned)(rr * AP + u * 8) * 2u, src);
    }
    asm volatile("cp.async.commit_group;" ::: "memory");
    asm volatile("cp.async.wait_group 0;" ::: "memory");
    __syncthreads();

    float oacc[8][4];
#pragma unroll
    for (int nt = 0; nt < 8; nt++)
#pragma unroll
        for (int r = 0; r < 4; r++) oacc[nt][r] = 0.f;
    float rs0 = 0.f, rs1 = 0.f;

    const int i0 = q0 + wq * 16 + qr;
    const int i1 = i0 + 8;
    const int m0 = hl * 64 + wq * 16 + qr;
    const float SC = 0.125f * 1.44269504088896f;

    int cur = 0;
    for (int ic = 0; ic < nch; ic++) {
        const int c = jstart + ic * CHK;
        if (ic + 1 < nch)
            stage_kv(sK + (cur ^ 1) * KV_BUF_B, sV + (cur ^ 1) * KV_BUF_B,
                     Kg, Vg, c + CHK, tid);
        asm volatile("cp.async.commit_group;" ::: "memory");
        asm volatile("cp.async.wait_group 1;" ::: "memory");
        __syncthreads();

        const unsigned sKb = sK + cur * KV_BUF_B;
        const unsigned sVb = sV + cur * KV_BUF_B;
        const bool full = (c - q0 >= -192) && (c - q0 <= 192);

        // S = Q K^T in two halves of 4 n-tiles (keeps sfr live range small)
#pragma unroll
        for (int hseg = 0; hseg < 2; hseg++) {
            float sfr[4][4];
#pragma unroll
            for (int nt = 0; nt < 4; nt++)
#pragma unroll
                for (int r = 0; r < 4; r++) sfr[nt][r] = 0.f;
#pragma unroll
            for (int ks = 0; ks < 4; ks++) {
                unsigned qa[4];
                ldsm_x4(qa, sQ + (q_e + ks * 16) * 2);
                unsigned kb[2][4];
#pragma unroll
                for (int n2 = 0; n2 < 2; n2++)
                    ldsm_x4(kb[n2], sKb + (k_e + (hseg * 2 + n2) * 16 * AP + ks * 16) * 2);
#pragma unroll
                for (int nt = 0; nt < 4; nt++) {
                    const int n2 = nt >> 1, od = nt & 1;
                    unsigned bf[2] = {kb[n2][od], kb[n2][od + 2]};
                    mma_fp16(sfr[nt], qa, bf);
                }
            }
            // exp + rowsum + store P for these 4 n-tiles
            if (full) {
#pragma unroll
                for (int nt = 0; nt < 4; nt++) {
                    const int ntg = hseg * 4 + nt;
                    float p00 = exp2f(sfr[nt][0] * SC);
                    float p01 = exp2f(sfr[nt][1] * SC);
                    float p10 = exp2f(sfr[nt][2] * SC);
                    float p11 = exp2f(sfr[nt][3] * SC);
                    rs0 += p00 + p01;
                    rs1 += p10 + p11;
                    *(__half2*)&Ps[m0 * AP + ntg * 8 + 2 * qc]       = __floats2half2_rn(p00, p01);
                    *(__half2*)&Ps[(m0 + 8) * AP + ntg * 8 + 2 * qc] = __floats2half2_rn(p10, p11);
                }
            } else {
#pragma unroll
                for (int nt = 0; nt < 4; nt++) {
                    const int ntg = hseg * 4 + nt;
                    const int j0 = c + ntg * 8 + 2 * qc;
                    const int j1 = j0 + 1;
                    float p00 = (j0 >= i0 - WINDOW_HALF && j0 < i0 + WINDOW_HALF) ? exp2f(sfr[nt][0] * SC) : 0.f;
                    float p01 = (j1 >= i0 - WINDOW_HALF && j1 < i0 + WINDOW_HALF) ? exp2f(sfr[nt][1] * SC) : 0.f;
                    float p10 = (j0 >= i1 - WINDOW_HALF && j0 < i1 + WINDOW_HALF) ? exp2f(sfr[nt][2] * SC) : 0.f;
                    float p11 = (j1 >= i1 - WINDOW_HALF && j1 < i1 + WINDOW_HALF) ? exp2f(sfr[nt][3] * SC) : 0.f;
                    rs0 += p00 + p01;
                    rs1 += p10 + p11;
                    *(__half2*)&Ps[m0 * AP + ntg * 8 + 2 * qc]       = __floats2half2_rn(p00, p01);
                    *(__half2*)&Ps[(m0 + 8) * AP + ntg * 8 + 2 * qc] = __floats2half2_rn(p10, p11);
                }
            }
        }
        __syncwarp();

        // O += P V
#pragma unroll
        for (int ks = 0; ks < 4; ks++) {
            unsigned pa[4];
            ldsm_x4(pa, sP + (q_e + ks * 16) * 2);
            unsigned vb[4][4];
#pragma unroll
            for (int n2 = 0; n2 < 4; n2++)
                ldsm_x4_t(vb[n2], sVb + (v_e + ks * 16 * AP + n2 * 16) * 2);
#pragma unroll
            for (int nt = 0; nt < 8; nt++) {
                const int n2 = nt >> 1, od = nt & 1;
                unsigned bf[2] = {vb[n2][od], vb[n2][od + 2]};
                mma_fp16(oacc[nt], pa, bf);
            }
        }
        __syncthreads();
        cur ^= 1;
    }

    rs0 += __shfl_xor_sync(0xffffffffu, rs0, 1);
    rs0 += __shfl_xor_sync(0xffffffffu, rs0, 2);
    rs1 += __shfl_xor_sync(0xffffffffu, rs1, 1);
    rs1 += __shfl_xor_sync(0xffffffffu, rs1, 2);
    const float inv0 = 1.f / rs0;
    const float inv1 = 1.f / rs1;

#pragma unroll
    for (int nt = 0; nt < 8; nt++) {
        const int col = (h0 + hl) * HEAD_DIM + nt * 8 + 2 * qc;
        *(__half2*)(Oh + (size_t)i0 * D_MODEL + col) =
            __floats2half2_rn(oacc[nt][0] * inv0, oacc[nt][1] * inv0);
        *(__half2*)(Oh + (size_t)i1 * D_MODEL + col) =
            __floats2half2_rn(oacc[nt][2] * inv1, oacc[nt][3] * inv1);
    }
}

// ---------------------------------------------------------------------------
// Launch
// ---------------------------------------------------------------------------
extern "C" void kernel_launch(void* const* d_in, const int* in_sizes, int n_in,
                              void* d_out, int out_size)
{
    const float* X  = (const float*)d_in[0];
    const float* Wq = (const float*)d_in[1];
    const float* Wk = (const float*)d_in[2];
    const float* Wv = (const float*)d_in[3];
    const float* Wo = (const float*)d_in[4];
    float* out = (float*)d_out;

    __half *Xh, *Wh, *Woh, *Oh, *Qhf, *Khf, *Vhf;
    cudaGetSymbolAddress((void**)&Xh,  g_Xh);
    cudaGetSymbolAddress((void**)&Wh,  g_Wh);
    cudaGetSymbolAddress((void**)&Woh, g_Woh);
    cudaGetSymbolAddress((void**)&Oh,  g_Oh);
    cudaGetSymbolAddress((void**)&Qhf, g_Qhf);
    cudaGetSymbolAddress((void**)&Khf, g_Khf);
    cudaGetSymbolAddress((void**)&Vhf, g_Vhf);

    static bool attr_set = false;
    if (!attr_set) {
        cudaFuncSetAttribute(gemm_fp1<__half>, cudaFuncAttributeMaxDynamicSharedMemorySize, GEMM_SMEM);
        cudaFuncSetAttribute(gemm_fp1<float>,  cudaFuncAttributeMaxDynamicSharedMemorySize, GEMM_SMEM);
        cudaFuncSetAttribute(attn_fp16,        cudaFuncAttributeMaxDynamicSharedMemorySize, ATTN_SMEM);
        cudaFuncSetAttribute(attn_fp16,        cudaFuncAttributePreferredSharedMemoryCarveout, 100);
        attr_set = true;
    }

    split_all<<<SPLIT_BLOCKS, 256>>>(X, Wq, Wk, Wv, Wo, Xh, Wh, Woh);

    gemm_fp1<__half><<<dim3(QKV_N / BN, T_SEQ / BM), 256, GEMM_SMEM>>>(
        Xh, Wh, D_MODEL,
        Qhf, D_MODEL, D_MODEL,
        Khf, D_MODEL + KV_DIM, KV_DIM,
        Vhf, KV_DIM);

    qkv_prep<<<(PREP_TOT + 255) / 256, 256>>>(Qhf, Khf);

    attn_fp16<<<dim3(T_SEQ / QT, N_HEADS / 2), 256, ATTN_SMEM>>>(Qhf, Khf, Vhf, Oh);

    gemm_fp1<float><<<dim3(D_MODEL / BN, T_SEQ / BM), 256, GEMM_SMEM>>>(
        Oh, Woh, D_MODEL,
        out, D_MODEL, D_MODEL,
        out, D_MODEL + 1, D_MODEL,
        out, D_MODEL);
}

// round 16
// speedup vs baseline: 1.0363x; 1.0363x over previous
#include <cuda_runtime.h>
#include <cuda_fp16.h>
#include <math.h>
#include <stdint.h>

// ---------------------------------------------------------------------------
// Problem constants
// ---------------------------------------------------------------------------
#define T_SEQ    2048
#define D_MODEL  2048
#define N_HEADS  32
#define N_KV     8
#define HEAD_DIM 64
#define KV_DIM   (N_KV * HEAD_DIM)       // 512
#define QKV_N    (D_MODEL + 2 * KV_DIM)  // 3072
#define WINDOW_HALF 256

// ---------------------------------------------------------------------------
// Scratch (device globals; no allocation allowed)
// ---------------------------------------------------------------------------
__device__ __half g_Qhf[(size_t)T_SEQ * D_MODEL];  // fp16 Q (roped in-place)
__device__ __half g_Khf[(size_t)T_SEQ * KV_DIM];   // fp16 K (roped in-place)
__device__ __half g_Vhf[(size_t)T_SEQ * KV_DIM];   // fp16 V (final)
__device__ __half g_Xh[(size_t)T_SEQ * D_MODEL];
__device__ __half g_Wh[(size_t)QKV_N * D_MODEL];
__device__ __half g_Woh[(size_t)D_MODEL * D_MODEL];
__device__ __half g_Oh[(size_t)T_SEQ * D_MODEL];
__device__ float  g_cos[T_SEQ * 32];
__device__ float  g_sin[T_SEQ * 32];

// ---------------------------------------------------------------------------
// helpers
// ---------------------------------------------------------------------------
__device__ __forceinline__ unsigned smem_u32(const void* p)
{
    unsigned a;
    asm("{ .reg .u64 t; cvta.to.shared.u64 t, %1; cvt.u32.u64 %0, t; }" : "=r"(a) : "l"(p));
    return a;
}

__device__ __forceinline__ void mma_fp16(float* c, const unsigned* a, const unsigned* b)
{
    asm volatile(
        "mma.sync.aligned.m16n8k16.row.col.f32.f16.f16.f32 "
        "{%0,%1,%2,%3}, {%4,%5,%6,%7}, {%8,%9}, {%0,%1,%2,%3};"
        : "+f"(c[0]), "+f"(c[1]), "+f"(c[2]), "+f"(c[3])
        : "r"(a[0]), "r"(a[1]), "r"(a[2]), "r"(a[3]),
          "r"(b[0]), "r"(b[1]));
}

__device__ __forceinline__ void ldsm_x4(unsigned* r, unsigned addr)
{
    asm volatile("ldmatrix.sync.aligned.m8n8.x4.shared.b16 {%0,%1,%2,%3}, [%4];"
                 : "=r"(r[0]), "=r"(r[1]), "=r"(r[2]), "=r"(r[3]) : "r"(addr));
}

__device__ __forceinline__ void ldsm_x4_t(unsigned* r, unsigned addr)
{
    asm volatile("ldmatrix.sync.aligned.m8n8.x4.trans.shared.b16 {%0,%1,%2,%3}, [%4];"
                 : "=r"(r[0]), "=r"(r[1]), "=r"(r[2]), "=r"(r[3]) : "r"(addr));
}

__device__ __forceinline__ void cp16(unsigned dst, const void* src)
{
    asm volatile("cp.async.ca.shared.global [%0], [%1], 16;" :: "r"(dst), "l"(src));
}

__device__ __forceinline__ unsigned h2u(__half2 h) { return *(unsigned*)&h; }

// ---------------------------------------------------------------------------
// Fused prep kernel #1: RoPE cos/sin tables (first TBL_BLOCKS blocks) +
// fp32->fp16 conversion of X, Wqkv, Wo (8 floats / thread).
// ---------------------------------------------------------------------------
#define TBL_N      (T_SEQ * 32)
#define TBL_BLOCKS (TBL_N / 256)          // 256
#define N8_X   (T_SEQ * D_MODEL / 8)
#define N8_WQ  (D_MODEL * D_MODEL / 8)
#define N8_WKV (KV_DIM * D_MODEL / 8)
#define N8_WO  (D_MODEL * D_MODEL / 8)
#define N8_TOT (N8_X + N8_WQ + 2 * N8_WKV + N8_WO)
#define SPLIT_BLOCKS (TBL_BLOCKS + (N8_TOT + 255) / 256)

__global__ void split_all(const float* __restrict__ X,  const float* __restrict__ Wq,
                          const float* __restrict__ Wk, const float* __restrict__ Wv,
                          const float* __restrict__ Wo,
                          __half* __restrict__ Xh, __half* __restrict__ Wh,
                          __half* __restrict__ Woh)
{
    if (blockIdx.x < TBL_BLOCKS) {
        int idx = blockIdx.x * blockDim.x + threadIdx.x;
        int i = idx & 31;
        int t = idx >> 5;
        double invf = exp2(-(double)i / 32.0 * 13.287712379549449392);
        double ang  = fmod((double)t * invf, 6.28318530717958647692);
        g_cos[idx] = cosf((float)ang);
        g_sin[idx] = sinf((float)ang);
        return;
    }
    int i = (blockIdx.x - TBL_BLOCKS) * blockDim.x + threadIdx.x;
    if (i >= N8_TOT) return;

    const float* s; __half* hp; int off;
    if (i < N8_X)                         { off = i;                           s = X;  hp = Xh; }
    else if (i < N8_X + N8_WQ)            { off = i - N8_X;                    s = Wq; hp = Wh; }
    else if (i < N8_X + N8_WQ + N8_WKV)   { off = i - N8_X - N8_WQ;            s = Wk;
                                            hp = Wh + (size_t)D_MODEL * D_MODEL; }
    else if (i < N8_X + N8_WQ + 2*N8_WKV) { off = i - N8_X - N8_WQ - N8_WKV;   s = Wv;
                                            hp = Wh + (size_t)(D_MODEL + KV_DIM) * D_MODEL; }
    else                                  { off = i - N8_X - N8_WQ - 2*N8_WKV; s = Wo; hp = Woh; }

    float4 v0 = ((const float4*)s)[2 * off];
    float4 v1 = ((const float4*)s)[2 * off + 1];
    uint4 w;
    w.x = h2u(__floats2half2_rn(v0.x, v0.y));
    w.y = h2u(__floats2half2_rn(v0.z, v0.w));
    w.z = h2u(__floats2half2_rn(v1.x, v1.y));
    w.w = h2u(__floats2half2_rn(v1.z, v1.w));
    ((uint4*)hp)[off] = w;
}

// ---------------------------------------------------------------------------
// fp16 single-pass tensor-core GEMM; output dtype templated (fp32 or fp16).
// ---------------------------------------------------------------------------
#define BM 128
#define BN 128
#define GBK 32
#define KPAD 40
#define PLANE_E (128 * KPAD)
#define PLANE_BYTES (PLANE_E * 2)
#define STAGE_B (2 * PLANE_BYTES)
#define GEMM_SMEM (2 * STAGE_B)

__device__ __forceinline__ void stage_fp(unsigned sbase,
                                         const __half* A, const __half* B,
                                         int K, int bm, int bn, int k0, int tid)
{
#pragma unroll
    for (int t = 0; t < 4; t++) {
        int id = tid + t * 256;
        int plane = id >> 9;
        int r = (id >> 2) & 127;
        int c = id & 3;
        unsigned dst = sbase + (unsigned)(plane * PLANE_E + r * KPAD + c * 8) * 2u;
        const __half* src = (plane == 0)
            ? A + (size_t)(bm + r) * K + k0 + c * 8
            : B + (size_t)(bn + r) * K + k0 + c * 8;
        cp16(dst, src);
    }
}

template<typename TO>
__global__ void __launch_bounds__(256, 2)
gemm_fp1(const __half* __restrict__ A, const __half* __restrict__ B, int K,
         TO* __restrict__ C0, int n0, int s0,
         TO* __restrict__ C1, int n1, int s1,
         TO* __restrict__ C2, int s2)
{
    extern __shared__ __half smb[];
    unsigned sbase = smem_u32(smb);

    const int tid = threadIdx.x;
    const int bm = blockIdx.y * BM;
    const int bn = blockIdx.x * BN;

    const int warp = tid >> 5;
    const int lane = tid & 31;
    const int qr = lane >> 2;
    const int qc = lane & 3;
    const int wr = warp >> 2;
    const int wc = warp & 3;

    const int lane8 = lane & 7;
    const int mat   = lane >> 3;
    const unsigned a_e = (unsigned)((wr * 64 + (mat & 1) * 8 + lane8) * KPAD + (mat >> 1) * 8);
    const unsigned b_e = (unsigned)((wc * 32 + (mat & 1) * 8 + lane8) * KPAD + (mat >> 1) * 8);

    float acc[4][4][4];
#pragma unroll
    for (int i = 0; i < 4; i++)
#pragma unroll
        for (int j = 0; j < 4; j++)
#pragma unroll
            for (int r = 0; r < 4; r++) acc[i][j][r] = 0.f;

    const int NS = K / GBK;

    stage_fp(sbase, A, B, K, bm, bn, 0, tid);
    asm volatile("cp.async.commit_group;" ::: "memory");
    stage_fp(sbase + STAGE_B, A, B, K, bm, bn, GBK, tid);
    asm volatile("cp.async.commit_group;" ::: "memory");

    for (int s = 0; s < NS; s++) {
        asm volatile("cp.async.wait_group 1;" ::: "memory");
        __syncthreads();

        const int buf = s & 1;
        const unsigned stg = sbase + buf * STAGE_B;
        const unsigned aP = stg + a_e * 2;
        const unsigned bP = stg + PLANE_BYTES + b_e * 2;

#pragma unroll
        for (int ks = 0; ks < GBK; ks += 16) {
            unsigned bh[2][4];
#pragma unroll
            for (int n2 = 0; n2 < 2; n2++)
                ldsm_x4(bh[n2], bP + n2 * (16 * KPAD * 2) + ks * 2);
#pragma unroll
            for (int mt = 0; mt < 4; mt++) {
                unsigned ah[4];
                ldsm_x4(ah, aP + mt * (16 * KPAD * 2) + ks * 2);
#pragma unroll
                for (int nt = 0; nt < 4; nt++) {
                    const int n2 = nt >> 1, od = nt & 1;
                    unsigned bf[2] = {bh[n2][od], bh[n2][od + 2]};
                    mma_fp16(acc[mt][nt], ah, bf);
                }
            }
        }
        __syncthreads();

        if (s + 2 < NS)
            stage_fp(sbase + buf * STAGE_B, A, B, K, bm, bn, (s + 2) * GBK, tid);
        asm volatile("cp.async.commit_group;" ::: "memory");
    }

    TO* C; int col0, stride;
    if (bn < n0)      { C = C0; col0 = bn;      stride = s0; }
    else if (bn < n1) { C = C1; col0 = bn - n0; stride = s1; }
    else              { C = C2; col0 = bn - n1; stride = s2; }

#pragma unroll
    for (int mt = 0; mt < 4; mt++) {
        const int row0 = bm + wr * 64 + mt * 16 + qr;
#pragma unroll
        for (int nt = 0; nt < 4; nt++) {
            const int col = col0 + wc * 32 + nt * 8 + qc * 2;
            if (sizeof(TO) == 2) {
                *(__half2*)((__half*)C + (size_t)row0       * stride + col) =
                    __floats2half2_rn(acc[mt][nt][0], acc[mt][nt][1]);
                *(__half2*)((__half*)C + (size_t)(row0 + 8) * stride + col) =
                    __floats2half2_rn(acc[mt][nt][2], acc[mt][nt][3]);
            } else {
                *(float2*)((float*)C + (size_t)row0       * stride + col) =
                    make_float2(acc[mt][nt][0], acc[mt][nt][1]);
                *(float2*)((float*)C + (size_t)(row0 + 8) * stride + col) =
                    make_float2(acc[mt][nt][2], acc[mt][nt][3]);
            }
        }
    }
}

// ---------------------------------------------------------------------------
// qkv_prep: in-place RoPE of fp16 Q (per head) and fp16 K (fp32 math).
// ---------------------------------------------------------------------------
#define PREP_Q  (T_SEQ * N_HEADS * 8)   // 524288
#define PREP_K  (T_SEQ * N_KV * 8)      // 131072
#define PREP_TOT (PREP_Q + PREP_K)

__device__ __forceinline__ void rope4_inplace(__half* p, const float* cs, const float* sn)
{
    __half2 a01 = *(__half2*)(p);
    __half2 a23 = *(__half2*)(p + 2);
    __half2 b01 = *(__half2*)(p + 32);
    __half2 b23 = *(__half2*)(p + 34);
    float2 a0 = __half22float2(a01), a1 = __half22float2(a23);
    float2 b0 = __half22float2(b01), b1 = __half22float2(b23);
    *(__half2*)(p)      = __floats2half2_rn(a0.x * cs[0] - b0.x * sn[0], a0.y * cs[1] - b0.y * sn[1]);
    *(__half2*)(p + 2)  = __floats2half2_rn(a1.x * cs[2] - b1.x * sn[2], a1.y * cs[3] - b1.y * sn[3]);
    *(__half2*)(p + 32) = __floats2half2_rn(b0.x * cs[0] + a0.x * sn[0], b0.y * cs[1] + a0.y * sn[1]);
    *(__half2*)(p + 34) = __floats2half2_rn(b1.x * cs[2] + a1.x * sn[2], b1.y * cs[3] + a1.y * sn[3]);
}

__global__ void qkv_prep(__half* __restrict__ Qhf, __half* __restrict__ Khf)
{
    int idx = blockIdx.x * blockDim.x + threadIdx.x;
    if (idx >= PREP_TOT) return;

    if (idx < PREP_Q) {
        int d4 = (idx & 7) * 4;
        int h  = (idx >> 3) & 31;
        int t  = idx >> 8;
        float4 cs = *(const float4*)(g_cos + t * 32 + d4);
        float4 sn = *(const float4*)(g_sin + t * 32 + d4);
        rope4_inplace(Qhf + (size_t)t * D_MODEL + h * HEAD_DIM + d4, (const float*)&cs, (const float*)&sn);
    } else {
        idx -= PREP_Q;
        int d4 = (idx & 7) * 4;
        int g  = (idx >> 3) & 7;
        int t  = idx >> 6;
        float4 cs = *(const float4*)(g_cos + t * 32 + d4);
        float4 sn = *(const float4*)(g_sin + t * 32 + d4);
        rope4_inplace(Khf + (size_t)t * KV_DIM + g * HEAD_DIM + d4, (const float*)&cs, (const float*)&sn);
    }
}

// ---------------------------------------------------------------------------
// fp16 tensor-core banded GQA attention: 2 heads / block, prepped fp16 Q/K/V,
// double-buffered K/V chunks. P never touches smem: the S C-fragments are
// exp'd and packed DIRECTLY into PV A-fragments (identical fp16 values to the
// old smem round-trip, so results are bit-identical).
// ---------------------------------------------------------------------------
#define QT  64
#define CHK 64
#define AP  72
#define Q_BYTES   (2 * QT * AP * 2)            // 18432
#define KV_BUF_B  (CHK * AP * 2)               // 9216
#define ATTN_SMEM (Q_BYTES + 4 * KV_BUF_B)     // 55296

__device__ __forceinline__ void stage_kv(unsigned dK, unsigned dV,
                                         const __half* Kg, const __half* Vg,
                                         int c, int tid)
{
    const int r  = tid >> 2;
    const int u0 = (tid & 3) * 2;
    const __half* ks = Kg + (size_t)(c + r) * KV_DIM;
    const __half* vs = Vg + (size_t)(c + r) * KV_DIM;
#pragma unroll
    for (int u = 0; u < 2; u++) {
        cp16(dK + (unsigned)(r * AP + (u0 + u) * 8) * 2u, ks + (u0 + u) * 8);
        cp16(dV + (unsigned)(r * AP + (u0 + u) * 8) * 2u, vs + (u0 + u) * 8);
    }
}

__global__ void __launch_bounds__(256)
attn_fp16(const __half* __restrict__ Qhf, const __half* __restrict__ Khf,
          const __half* __restrict__ Vhf, __half* __restrict__ Oh)
{
    extern __shared__ __half smA[];
    const unsigned sQ = smem_u32(smA);
    const unsigned sK = sQ + Q_BYTES;
    const unsigned sV = sK + 2 * KV_BUF_B;

    const int h0 = blockIdx.y * 2;
    const int g  = h0 >> 2;
    const int q0 = blockIdx.x * QT;
    const int tid = threadIdx.x;
    const int w = tid >> 5;
    const int lane = tid & 31;
    const int qr = lane >> 2;
    const int qc = lane & 3;
    const int lane8 = lane & 7;
    const int mat   = lane >> 3;

    const int hl = w >> 2;
    const int wq = w & 3;

    const unsigned q_e = (unsigned)((hl * 64 + wq * 16 + (mat & 1) * 8 + lane8) * AP + (mat >> 1) * 8);
    const unsigned k_e = (unsigned)(((mat & 1) * 8 + lane8) * AP + (mat >> 1) * 8);
    const unsigned v_e = (unsigned)(((mat >> 1) * 8 + lane8) * AP + (mat & 1) * 8);

    const __half* Kg = Khf + g * HEAD_DIM;
    const __half* Vg = Vhf + g * HEAD_DIM;

    const int jstart = max(0, q0 - WINDOW_HALF);
    const int jend   = min(T_SEQ, q0 + QT + WINDOW_HALF);
    const int nch    = (jend - jstart) / CHK;

    stage_kv(sK, sV, Kg, Vg, jstart, tid);
    asm volatile("cp.async.commit_group;" ::: "memory");
#pragma unroll
    for (int t = 0; t < 4; t++) {
        int idx = tid + t * 256;
        int rr  = idx >> 3;
        int u   = idx & 7;
        int hloc = rr >> 6;
        int r    = rr & 63;
        const __half* src = Qhf + (size_t)(q0 + r) * D_MODEL + (h0 + hloc) * HEAD_DIM + u * 8;
        cp16(sQ + (unsigned)(rr * AP + u * 8) * 2u, src);
    }
    asm volatile("cp.async.commit_group;" ::: "memory");
    asm volatile("cp.async.wait_group 0;" ::: "memory");
    __syncthreads();

    // hoist Q A-fragments for all 4 k-steps (Qs never overwritten)
    unsigned qa[4][4];
#pragma unroll
    for (int ks = 0; ks < 4; ks++)
        ldsm_x4(qa[ks], sQ + (q_e + ks * 16) * 2);

    float oacc[8][4];
#pragma unroll
    for (int nt = 0; nt < 8; nt++)
#pragma unroll
        for (int r = 0; r < 4; r++) oacc[nt][r] = 0.f;
    float rs0 = 0.f, rs1 = 0.f;

    const int i0 = q0 + wq * 16 + qr;
    const int i1 = i0 + 8;
    const float SC = 0.125f * 1.44269504088896f;

    int cur = 0;
    for (int ic = 0; ic < nch; ic++) {
        const int c = jstart + ic * CHK;
        if (ic + 1 < nch)
            stage_kv(sK + (cur ^ 1) * KV_BUF_B, sV + (cur ^ 1) * KV_BUF_B,
                     Kg, Vg, c + CHK, tid);
        asm volatile("cp.async.commit_group;" ::: "memory");
        asm volatile("cp.async.wait_group 1;" ::: "memory");
        __syncthreads();

        const unsigned sKb = sK + cur * KV_BUF_B;
        const unsigned sVb = sV + cur * KV_BUF_B;

        // S = Q K^T
        float sfr[8][4];
#pragma unroll
        for (int nt = 0; nt < 8; nt++)
#pragma unroll
            for (int r = 0; r < 4; r++) sfr[nt][r] = 0.f;
#pragma unroll
        for (int ks = 0; ks < 4; ks++) {
            unsigned kb[4][4];
#pragma unroll
            for (int n2 = 0; n2 < 4; n2++)
                ldsm_x4(kb[n2], sKb + (k_e + n2 * 16 * AP + ks * 16) * 2);
#pragma unroll
            for (int nt = 0; nt < 8; nt++) {
                const int n2 = nt >> 1, od = nt & 1;
                unsigned bf[2] = {kb[n2][od], kb[n2][od + 2]};
                mma_fp16(sfr[nt], qa[ks], bf);
            }
        }

        // exp + rowsum; pack P C-frags DIRECTLY into PV A-frags:
        //   pa[ks] = { h2(p00,p01)[nt=2ks], h2(p10,p11)[nt=2ks],
        //              h2(p00,p01)[nt=2ks+1], h2(p10,p11)[nt=2ks+1] }
        unsigned pa[4][4];
        const bool full = (c - q0 >= -192) && (c - q0 <= 192);
        if (full) {
#pragma unroll
            for (int nt = 0; nt < 8; nt++) {
                float p00 = exp2f(sfr[nt][0] * SC);
                float p01 = exp2f(sfr[nt][1] * SC);
                float p10 = exp2f(sfr[nt][2] * SC);
                float p11 = exp2f(sfr[nt][3] * SC);
                rs0 += p00 + p01;
                rs1 += p10 + p11;
                pa[nt >> 1][(nt & 1) * 2]     = h2u(__floats2half2_rn(p00, p01));
                pa[nt >> 1][(nt & 1) * 2 + 1] = h2u(__floats2half2_rn(p10, p11));
            }
        } else {
#pragma unroll
            for (int nt = 0; nt < 8; nt++) {
                const int j0 = c + nt * 8 + 2 * qc;
                const int j1 = j0 + 1;
                float p00 = (j0 >= i0 - WINDOW_HALF && j0 < i0 + WINDOW_HALF) ? exp2f(sfr[nt][0] * SC) : 0.f;
                float p01 = (j1 >= i0 - WINDOW_HALF && j1 < i0 + WINDOW_HALF) ? exp2f(sfr[nt][1] * SC) : 0.f;
                float p10 = (j0 >= i1 - WINDOW_HALF && j0 < i1 + WINDOW_HALF) ? exp2f(sfr[nt][2] * SC) : 0.f;
                float p11 = (j1 >= i1 - WINDOW_HALF && j1 < i1 + WINDOW_HALF) ? exp2f(sfr[nt][3] * SC) : 0.f;
                rs0 += p00 + p01;
                rs1 += p10 + p11;
                pa[nt >> 1][(nt & 1) * 2]     = h2u(__floats2half2_rn(p00, p01));
                pa[nt >> 1][(nt & 1) * 2 + 1] = h2u(__floats2half2_rn(p10, p11));
            }
        }

        // O += P V  (A fragments straight from registers)
#pragma unroll
        for (int ks = 0; ks < 4; ks++) {
            unsigned vb[4][4];
#pragma unroll
            for (int n2 = 0; n2 < 4; n2++)
                ldsm_x4_t(vb[n2], sVb + (v_e + ks * 16 * AP + n2 * 16) * 2);
#pragma unroll
            for (int nt = 0; nt < 8; nt++) {
                const int n2 = nt >> 1, od = nt & 1;
                unsigned bf[2] = {vb[n2][od], vb[n2][od + 2]};
                mma_fp16(oacc[nt], pa[ks], bf);
            }
        }
        __syncthreads();   // all reads of buf `cur` done before it is restaged
        cur ^= 1;
    }

    rs0 += __shfl_xor_sync(0xffffffffu, rs0, 1);
    rs0 += __shfl_xor_sync(0xffffffffu, rs0, 2);
    rs1 += __shfl_xor_sync(0xffffffffu, rs1, 1);
    rs1 += __shfl_xor_sync(0xffffffffu, rs1, 2);
    const float inv0 = 1.f / rs0;
    const float inv1 = 1.f / rs1;

#pragma unroll
    for (int nt = 0; nt < 8; nt++) {
        const int col = (h0 + hl) * HEAD_DIM + nt * 8 + 2 * qc;
        *(__half2*)(Oh + (size_t)i0 * D_MODEL + col) =
            __floats2half2_rn(oacc[nt][0] * inv0, oacc[nt][1] * inv0);
        *(__half2*)(Oh + (size_t)i1 * D_MODEL + col) =
            __floats2half2_rn(oacc[nt][2] * inv1, oacc[nt][3] * inv1);
    }
}

// ---------------------------------------------------------------------------
// Launch
// ---------------------------------------------------------------------------
extern "C" void kernel_launch(void* const* d_in, const int* in_sizes, int n_in,
                              void* d_out, int out_size)
{
    const float* X  = (const float*)d_in[0];
    const float* Wq = (const float*)d_in[1];
    const float* Wk = (const float*)d_in[2];
    const float* Wv = (const float*)d_in[3];
    const float* Wo = (const float*)d_in[4];
    float* out = (float*)d_out;

    __half *Xh, *Wh, *Woh, *Oh, *Qhf, *Khf, *Vhf;
    cudaGetSymbolAddress((void**)&Xh,  g_Xh);
    cudaGetSymbolAddress((void**)&Wh,  g_Wh);
    cudaGetSymbolAddress((void**)&Woh, g_Woh);
    cudaGetSymbolAddress((void**)&Oh,  g_Oh);
    cudaGetSymbolAddress((void**)&Qhf, g_Qhf);
    cudaGetSymbolAddress((void**)&Khf, g_Khf);
    cudaGetSymbolAddress((void**)&Vhf, g_Vhf);

    static bool attr_set = false;
    if (!attr_set) {
        cudaFuncSetAttribute(gemm_fp1<__half>, cudaFuncAttributeMaxDynamicSharedMemorySize, GEMM_SMEM);
        cudaFuncSetAttribute(gemm_fp1<float>,  cudaFuncAttributeMaxDynamicSharedMemorySize, GEMM_SMEM);
        cudaFuncSetAttribute(attn_fp16,        cudaFuncAttributeMaxDynamicSharedMemorySize, ATTN_SMEM);
        attr_set = true;
    }

    split_all<<<SPLIT_BLOCKS, 256>>>(X, Wq, Wk, Wv, Wo, Xh, Wh, Woh);

    gemm_fp1<__half><<<dim3(QKV_N / BN, T_SEQ / BM), 256, GEMM_SMEM>>>(
        Xh, Wh, D_MODEL,
        Qhf, D_MODEL, D_MODEL,
        Khf, D_MODEL + KV_DIM, KV_DIM,
        Vhf, KV_DIM);

    qkv_prep<<<(PREP_TOT + 255) / 256, 256>>>(Qhf, Khf);

    attn_fp16<<<dim3(T_SEQ / QT, N_HEADS / 2), 256, ATTN_SMEM>>>(Qhf, Khf, Vhf, Oh);

    gemm_fp1<float><<<dim3(D_MODEL / BN, T_SEQ / BM), 256, GEMM_SMEM>>>(
        Oh, Woh, D_MODEL,
        out, D_MODEL, D_MODEL,
        out, D_MODEL + 1, D_MODEL,
        out, D_MODEL);
}